// round 13
// baseline (speedup 1.0000x reference)
#include <cuda_runtime.h>
#include <cuda_bf16.h>

// ---------------------------------------------------------------------------
// GNN_23630910062676: 2-layer GCN, pull-based aggregation via CSR.
//   degi histogram -> exclusive scan -> bucket fill (CSR by dst)
//   layer1: FUSED per-block pull-aggregate(x) -> smem -> GEMM -> relu(H)
//   layer2: GEMM (H@W2 -> G), pull-aggregate(G) + bias -> out
// R12: agg+gemm1 fusion (no AX round-trip), scan2 folded into scan3.
// ---------------------------------------------------------------------------

#define N_NODES 50000
#define N_EDGES 800000
#define DIN  64
#define DHID 128
#define DOUT 64

#define SCAN_BS 512
#define SCAN_NB ((N_NODES + SCAN_BS - 1) / SCAN_BS)   // 98

__device__ int   g_degi[N_NODES];
__device__ int   g_off [N_NODES + 1];
__device__ int   g_cur [N_NODES];
__device__ int   g_bsum[SCAN_NB];
__device__ int   g_col [N_EDGES];
__device__ float g_dinv[N_NODES];
__device__ float g_H   [N_NODES * DHID];
__device__ float g_G   [N_NODES * DOUT];

// ---------------------------------------------------------------------------
__global__ void k_count(const int* __restrict__ dst) {
    int e = blockIdx.x * blockDim.x + threadIdx.x;
    int e2 = e + (N_EDGES / 2);
    if (e < N_EDGES / 2) {
        atomicAdd(&g_degi[dst[e]], 1);
        atomicAdd(&g_degi[dst[e2]], 1);
    }
}

// Per-block inclusive scan, writes block-exclusive offsets + raw block sums
__global__ void k_scan1() {
    __shared__ int sh[SCAN_BS];
    int gid = blockIdx.x * SCAN_BS + threadIdx.x;
    int v = (gid < N_NODES) ? g_degi[gid] : 0;
    sh[threadIdx.x] = v;
    __syncthreads();
    #pragma unroll
    for (int off = 1; off < SCAN_BS; off <<= 1) {
        int t = (threadIdx.x >= off) ? sh[threadIdx.x - off] : 0;
        __syncthreads();
        sh[threadIdx.x] += t;
        __syncthreads();
    }
    if (gid < N_NODES) g_off[gid] = sh[threadIdx.x] - v;   // exclusive within block
    if (threadIdx.x == SCAN_BS - 1) g_bsum[blockIdx.x] = sh[SCAN_BS - 1];
}

// Finalize: each 256-node block computes its own bsum prefix (one reduce),
// then offsets, cursors, dinv. (scan2 folded in.)
__global__ void k_scan3() {
    __shared__ int sred[256];
    int t = threadIdx.x;
    int need = blockIdx.x >> 1;              // this block's range is inside scan1 block (b>>1)
    int v = (t < need) ? g_bsum[t] : 0;      // need <= 97 < 256
    sred[t] = v;
    __syncthreads();
    #pragma unroll
    for (int off = 128; off >= 1; off >>= 1) {
        if (t < off) sred[t] += sred[t + off];
        __syncthreads();
    }
    int prefix = sred[0];
    int i = blockIdx.x * 256 + t;
    if (i < N_NODES) {
        int o = g_off[i] + prefix;
        g_off[i] = o;
        g_cur[i] = o;
        g_dinv[i] = rsqrtf((float)(g_degi[i] + 1));
    }
    if (i == 0) g_off[N_NODES] = N_EDGES;
}

__global__ void k_fill(const int* __restrict__ src, const int* __restrict__ dst) {
    int e = blockIdx.x * blockDim.x + threadIdx.x;
    int e2 = e + (N_EDGES / 2);
    if (e < N_EDGES / 2) {
        int p  = atomicAdd(&g_cur[dst[e]], 1);
        g_col[p] = src[e];
        int p2 = atomicAdd(&g_cur[dst[e2]], 1);
        g_col[p2] = src[e2];
    }
}

// ---------------------------------------------------------------------------
// FUSED layer 1: per block, pull-aggregate 128 nodes of x into smem sA[row][k],
// then GEMM: H = relu(sA @ W1 + b1). 256 threads.
__global__ void __launch_bounds__(256) k_agg_gemm1(const float* __restrict__ x,
                                                   const float* __restrict__ W1,
                                                   const float* __restrict__ b1) {
    __shared__ float sA[128 * DIN];   // [row][k] 32 KB
    __shared__ float sB[DIN * DHID];  // [k][col] 32 KB
    int t = threadIdx.x;
    int row0 = blockIdx.x * 128;

    for (int i = t; i < DIN * DHID; i += 256) sB[i] = W1[i];

    // ---- aggregation phase: warp per node, 16 nodes per warp ----
    int w = t >> 5, l = t & 31;
    const float2* x2 = reinterpret_cast<const float2*>(x);
    for (int nn = 0; nn < 16; nn++) {
        int r = w * 16 + nn;
        int n = row0 + r;
        float ax = 0.f, ay = 0.f;
        if (n < N_NODES) {
            float dn = g_dinv[n];
            float2 v = x2[(size_t)n * 32 + l];
            ax = v.x * dn; ay = v.y * dn;
            int e = g_off[n], end = g_off[n + 1];
            for (; e + 4 <= end; e += 4) {
                int s0 = g_col[e], s1 = g_col[e + 1], s2 = g_col[e + 2], s3 = g_col[e + 3];
                float d0 = g_dinv[s0], d1 = g_dinv[s1], d2 = g_dinv[s2], d3 = g_dinv[s3];
                float2 u0 = x2[(size_t)s0 * 32 + l];
                float2 u1 = x2[(size_t)s1 * 32 + l];
                float2 u2 = x2[(size_t)s2 * 32 + l];
                float2 u3 = x2[(size_t)s3 * 32 + l];
                ax = fmaf(u0.x, d0, ax); ay = fmaf(u0.y, d0, ay);
                ax = fmaf(u1.x, d1, ax); ay = fmaf(u1.y, d1, ay);
                ax = fmaf(u2.x, d2, ax); ay = fmaf(u2.y, d2, ay);
                ax = fmaf(u3.x, d3, ax); ay = fmaf(u3.y, d3, ay);
            }
            for (; e < end; e++) {
                int s = g_col[e];
                float ds = g_dinv[s];
                float2 u = x2[(size_t)s * 32 + l];
                ax = fmaf(u.x, ds, ax); ay = fmaf(u.y, ds, ay);
            }
            ax *= dn; ay *= dn;
        }
        // [row][k] layout: lane l owns features 2l, 2l+1 -> conflict-free float2 store
        reinterpret_cast<float2*>(&sA[r * DIN])[l] = make_float2(ax, ay);
    }
    __syncthreads();

    // ---- GEMM phase: 8x8 tile per thread, scalar sA reads ([row][k]) ----
    int tc = t & 15, tr = t >> 4;
    int c0 = tc * 8, r0 = tr * 8;
    float acc[8][8];
    #pragma unroll
    for (int r = 0; r < 8; r++)
        #pragma unroll
        for (int c = 0; c < 8; c++) acc[r][c] = 0.f;

    #pragma unroll 4
    for (int k = 0; k < DIN; k++) {
        float a[8];
        #pragma unroll
        for (int i = 0; i < 8; i++) a[i] = sA[(r0 + i) * DIN + k];
        float4 q0 = *reinterpret_cast<float4*>(&sB[k * DHID + c0]);
        float4 q1 = *reinterpret_cast<float4*>(&sB[k * DHID + c0 + 4]);
        float b[8] = {q0.x, q0.y, q0.z, q0.w, q1.x, q1.y, q1.z, q1.w};
        #pragma unroll
        for (int r = 0; r < 8; r++)
            #pragma unroll
            for (int c = 0; c < 8; c++) acc[r][c] = fmaf(a[r], b[c], acc[r][c]);
    }

    float bias[8];
    #pragma unroll
    for (int c = 0; c < 8; c++) bias[c] = __ldg(&b1[c0 + c]);

    #pragma unroll
    for (int r = 0; r < 8; r++) {
        int grow = row0 + r0 + r;
        if (grow >= N_NODES) break;
        float4 o0, o1;
        o0.x = fmaxf(acc[r][0] + bias[0], 0.f);
        o0.y = fmaxf(acc[r][1] + bias[1], 0.f);
        o0.z = fmaxf(acc[r][2] + bias[2], 0.f);
        o0.w = fmaxf(acc[r][3] + bias[3], 0.f);
        o1.x = fmaxf(acc[r][4] + bias[4], 0.f);
        o1.y = fmaxf(acc[r][5] + bias[5], 0.f);
        o1.z = fmaxf(acc[r][6] + bias[6], 0.f);
        o1.w = fmaxf(acc[r][7] + bias[7], 0.f);
        float* dstp = g_H + (size_t)grow * DHID + c0;
        reinterpret_cast<float4*>(dstp)[0] = o0;
        reinterpret_cast<float4*>(dstp)[1] = o1;
    }
}

// ---------------------------------------------------------------------------
// GEMM2: G[N,64] = H[N,128] @ W2[128,64]
// Block: 128 rows x 64 cols, 256 threads, 8x4 tile, K in two 64-chunks.
__global__ void __launch_bounds__(256) k_gemm2(const float* __restrict__ W2) {
    __shared__ float sA[64 * 128];    // [k-chunk][row] 32 KB
    __shared__ float sB[DHID * DOUT]; // [k][col] 32 KB
    int t = threadIdx.x;
    int row0 = blockIdx.x * 128;

    for (int i = t; i < DHID * DOUT; i += 256) sB[i] = W2[i];

    int tc = t & 15, tr = t >> 4;
    int c0 = tc * 4, r0 = tr * 8;
    float acc[8][4];
    #pragma unroll
    for (int r = 0; r < 8; r++)
        #pragma unroll
        for (int c = 0; c < 4; c++) acc[r][c] = 0.f;

    #pragma unroll
    for (int ch = 0; ch < 2; ch++) {
        __syncthreads();
        for (int i = t; i < 128 * 16; i += 256) {
            int r = i >> 4, kq = i & 15;
            float4 v = make_float4(0.f, 0.f, 0.f, 0.f);
            if (row0 + r < N_NODES)
                v = reinterpret_cast<const float4*>(g_H + (size_t)(row0 + r) * DHID)
                        [ch * 16 + kq];
            sA[(kq * 4 + 0) * 128 + r] = v.x;
            sA[(kq * 4 + 1) * 128 + r] = v.y;
            sA[(kq * 4 + 2) * 128 + r] = v.z;
            sA[(kq * 4 + 3) * 128 + r] = v.w;
        }
        __syncthreads();

        #pragma unroll 4
        for (int k = 0; k < 64; k++) {
            float4 a0 = *reinterpret_cast<float4*>(&sA[k * 128 + r0]);
            float4 a1 = *reinterpret_cast<float4*>(&sA[k * 128 + r0 + 4]);
            float4 q0 = *reinterpret_cast<float4*>(&sB[(ch * 64 + k) * DOUT + c0]);
            float a[8] = {a0.x, a0.y, a0.z, a0.w, a1.x, a1.y, a1.z, a1.w};
            float b[4] = {q0.x, q0.y, q0.z, q0.w};
            #pragma unroll
            for (int r = 0; r < 8; r++)
                #pragma unroll
                for (int c = 0; c < 4; c++) acc[r][c] = fmaf(a[r], b[c], acc[r][c]);
        }
    }

    #pragma unroll
    for (int r = 0; r < 8; r++) {
        int grow = row0 + r0 + r;
        if (grow >= N_NODES) break;
        float4 gv = make_float4(acc[r][0], acc[r][1], acc[r][2], acc[r][3]);
        reinterpret_cast<float4*>(g_G + (size_t)grow * DOUT + c0)[0] = gv;
    }
}

// ---------------------------------------------------------------------------
// Pull aggregation of G into out (+bias). Warp per node, float2 lanes.
__global__ void __launch_bounds__(256) k_agg2(const float* __restrict__ b2,
                                              float* __restrict__ out) {
    const float2* G2 = reinterpret_cast<const float2*>(g_G);
    int n = blockIdx.x * 8 + (threadIdx.x >> 5);
    if (n >= N_NODES) return;
    int l = threadIdx.x & 31;
    float dn = g_dinv[n];
    float2 v = G2[(size_t)n * 32 + l];
    float ax = v.x * dn, ay = v.y * dn;
    int e = g_off[n], end = g_off[n + 1];
    for (; e + 4 <= end; e += 4) {
        int s0 = g_col[e], s1 = g_col[e + 1], s2 = g_col[e + 2], s3 = g_col[e + 3];
        float d0 = g_dinv[s0], d1 = g_dinv[s1], d2 = g_dinv[s2], d3 = g_dinv[s3];
        float2 u0 = G2[(size_t)s0 * 32 + l];
        float2 u1 = G2[(size_t)s1 * 32 + l];
        float2 u2 = G2[(size_t)s2 * 32 + l];
        float2 u3 = G2[(size_t)s3 * 32 + l];
        ax = fmaf(u0.x, d0, ax); ay = fmaf(u0.y, d0, ay);
        ax = fmaf(u1.x, d1, ax); ay = fmaf(u1.y, d1, ay);
        ax = fmaf(u2.x, d2, ax); ay = fmaf(u2.y, d2, ay);
        ax = fmaf(u3.x, d3, ax); ay = fmaf(u3.y, d3, ay);
    }
    for (; e < end; e++) {
        int s = g_col[e];
        float ds = g_dinv[s];
        float2 u = G2[(size_t)s * 32 + l];
        ax = fmaf(u.x, ds, ax); ay = fmaf(u.y, ds, ay);
    }
    float2 bb = reinterpret_cast<const float2*>(b2)[l];
    float2 o = make_float2(fmaf(ax, dn, bb.x), fmaf(ay, dn, bb.y));
    reinterpret_cast<float2*>(out)[(size_t)n * 32 + l] = o;
}

// ---------------------------------------------------------------------------
extern "C" void kernel_launch(void* const* d_in, const int* in_sizes, int n_in,
                              void* d_out, int out_size) {
    const float* x  = (const float*)d_in[0];
    const int*   ei = (const int*)d_in[1];      // [2, E]
    const float* W1 = (const float*)d_in[2];
    const float* b1 = (const float*)d_in[3];
    const float* W2 = (const float*)d_in[4];
    const float* b2 = (const float*)d_in[5];
    float* out = (float*)d_out;

    const int* src = ei;
    const int* dst = ei + N_EDGES;

    // CSR build (reused by both layers) + dinv
    int* degi_ptr = nullptr;
    cudaGetSymbolAddress((void**)&degi_ptr, g_degi);
    cudaMemsetAsync(degi_ptr, 0, N_NODES * sizeof(int));

    k_count    <<<(N_EDGES / 2 + 255) / 256, 256>>>(dst);
    k_scan1    <<<SCAN_NB, SCAN_BS>>>();
    k_scan3    <<<(N_NODES + 255) / 256, 256>>>();
    k_fill     <<<(N_EDGES / 2 + 255) / 256, 256>>>(src, dst);

    // layer 1: fused pull-aggregate + GEMM (+bias+relu)
    k_agg_gemm1<<<(N_NODES + 127) / 128, 256>>>(x, W1, b1);

    // layer 2: GEMM (128 -> 64), then pull-aggregate into out (+bias fused)
    k_gemm2    <<<(N_NODES + 127) / 128, 256>>>(W2);
    k_agg2     <<<(N_NODES + 7) / 8, 256>>>(b2, out);
}

// round 14
// speedup vs baseline: 1.2406x; 1.2406x over previous
#include <cuda_runtime.h>
#include <cuda_bf16.h>

// ---------------------------------------------------------------------------
// GNN_23630910062676: 2-layer GCN, pull-based aggregation via CSR.
//   degi histogram (with tickets) -> exclusive scan -> atomic-free bucket fill
//   AX[n] = dinv[n]*(dinv[n]*x[n] + sum_s dinv[s]*x[s])
//   H = relu(AX @ W1 + b1) ; G = H @ W2
//   out[n] = b2 + dinv[n]*(dinv[n]*G[n] + sum_s dinv[s]*G[s])
// R14: revert R12 fusion (regressed); R11 agg/GEMM kernels + ticket-based
//      CSR fill (no atomics in fill) + scan2 folded into scan3.
// ---------------------------------------------------------------------------

#define N_NODES 50000
#define N_EDGES 800000
#define DIN  64
#define DHID 128
#define DOUT 64

#define SCAN_BS 512
#define SCAN_NB ((N_NODES + SCAN_BS - 1) / SCAN_BS)   // 98

__device__ int   g_degi[N_NODES];
__device__ int   g_off [N_NODES + 1];
__device__ int   g_bsum[SCAN_NB];
__device__ int   g_tick[N_EDGES];
__device__ int   g_col [N_EDGES];
__device__ float g_dinv[N_NODES];
__device__ float g_AX  [N_NODES * DIN];
__device__ float g_H   [N_NODES * DHID];
__device__ float g_G   [N_NODES * DOUT];

// ---------------------------------------------------------------------------
// Histogram + ticket: remember each edge's position within its dst bucket.
__global__ void k_count(const int* __restrict__ dst) {
    int e = blockIdx.x * blockDim.x + threadIdx.x;
    int e2 = e + (N_EDGES / 2);
    if (e < N_EDGES / 2) {
        g_tick[e]  = atomicAdd(&g_degi[dst[e]], 1);
        g_tick[e2] = atomicAdd(&g_degi[dst[e2]], 1);
    }
}

// Per-block inclusive scan, writes block-exclusive offsets + raw block sums
__global__ void k_scan1() {
    __shared__ int sh[SCAN_BS];
    int gid = blockIdx.x * SCAN_BS + threadIdx.x;
    int v = (gid < N_NODES) ? g_degi[gid] : 0;
    sh[threadIdx.x] = v;
    __syncthreads();
    #pragma unroll
    for (int off = 1; off < SCAN_BS; off <<= 1) {
        int t = (threadIdx.x >= off) ? sh[threadIdx.x - off] : 0;
        __syncthreads();
        sh[threadIdx.x] += t;
        __syncthreads();
    }
    if (gid < N_NODES) g_off[gid] = sh[threadIdx.x] - v;   // exclusive within block
    if (threadIdx.x == SCAN_BS - 1) g_bsum[blockIdx.x] = sh[SCAN_BS - 1];
}

// Finalize: each 256-node block reduces its own bsum prefix (scan2 folded in),
// then writes offsets + dinv. Block b's nodes all lie in scan1 block b>>1.
__global__ void k_scan3() {
    __shared__ int sred[256];
    int t = threadIdx.x;
    int need = blockIdx.x >> 1;
    int v = (t < need) ? g_bsum[t] : 0;      // need <= 97 < 256
    sred[t] = v;
    __syncthreads();
    #pragma unroll
    for (int off = 128; off >= 1; off >>= 1) {
        if (t < off) sred[t] += sred[t + off];
        __syncthreads();
    }
    int prefix = sred[0];
    int i = blockIdx.x * 256 + t;
    if (i < N_NODES) {
        g_off[i] = g_off[i] + prefix;
        g_dinv[i] = rsqrtf((float)(g_degi[i] + 1));
    }
    if (i == 0) g_off[N_NODES] = N_EDGES;
}

// Atomic-free fill using tickets.
__global__ void k_fill(const int* __restrict__ src, const int* __restrict__ dst) {
    int e = blockIdx.x * blockDim.x + threadIdx.x;
    int e2 = e + (N_EDGES / 2);
    if (e < N_EDGES / 2) {
        g_col[g_off[dst[e]]  + g_tick[e]]  = src[e];
        g_col[g_off[dst[e2]] + g_tick[e2]] = src[e2];
    }
}

// ---------------------------------------------------------------------------
// Pull aggregation over a 64-wide tensor: ONE WARP per node, float2 per lane.
#define AGG_BODY(SRC2, EPILOGUE)                                                \
    int n = blockIdx.x * 8 + (threadIdx.x >> 5);                                \
    if (n >= N_NODES) return;                                                   \
    int l = threadIdx.x & 31;                                                   \
    float dn = g_dinv[n];                                                       \
    float2 v = (SRC2)[(size_t)n * 32 + l];                                      \
    float ax = v.x * dn, ay = v.y * dn;                                         \
    int e = g_off[n], end = g_off[n + 1];                                       \
    for (; e + 4 <= end; e += 4) {                                              \
        int s0 = g_col[e], s1 = g_col[e + 1], s2 = g_col[e + 2], s3 = g_col[e + 3]; \
        float d0 = g_dinv[s0], d1 = g_dinv[s1], d2 = g_dinv[s2], d3 = g_dinv[s3];   \
        float2 u0 = (SRC2)[(size_t)s0 * 32 + l];                                \
        float2 u1 = (SRC2)[(size_t)s1 * 32 + l];                                \
        float2 u2 = (SRC2)[(size_t)s2 * 32 + l];                                \
        float2 u3 = (SRC2)[(size_t)s3 * 32 + l];                                \
        ax = fmaf(u0.x, d0, ax); ay = fmaf(u0.y, d0, ay);                       \
        ax = fmaf(u1.x, d1, ax); ay = fmaf(u1.y, d1, ay);                       \
        ax = fmaf(u2.x, d2, ax); ay = fmaf(u2.y, d2, ay);                       \
        ax = fmaf(u3.x, d3, ax); ay = fmaf(u3.y, d3, ay);                       \
    }                                                                           \
    for (; e < end; e++) {                                                      \
        int s = g_col[e];                                                       \
        float ds = g_dinv[s];                                                   \
        float2 u = (SRC2)[(size_t)s * 32 + l];                                  \
        ax = fmaf(u.x, ds, ax); ay = fmaf(u.y, ds, ay);                         \
    }                                                                           \
    EPILOGUE

__global__ void __launch_bounds__(256) k_aggX(const float* __restrict__ x) {
    const float2* x2 = reinterpret_cast<const float2*>(x);
    AGG_BODY(x2,
             {
                 float2 o = make_float2(ax * dn, ay * dn);
                 reinterpret_cast<float2*>(g_AX)[(size_t)n * 32 + l] = o;
             })
}

__global__ void __launch_bounds__(256) k_agg2(const float* __restrict__ b2,
                                              float* __restrict__ out) {
    const float2* G2 = reinterpret_cast<const float2*>(g_G);
    AGG_BODY(G2,
             {
                 float2 bb = reinterpret_cast<const float2*>(b2)[l];
                 float2 o = make_float2(fmaf(ax, dn, bb.x), fmaf(ay, dn, bb.y));
                 reinterpret_cast<float2*>(out)[(size_t)n * 32 + l] = o;
             })
}

// ---------------------------------------------------------------------------
// GEMM1: H[N,128] = relu(AX[N,64] @ W1[64,128] + b1)
// Block: 128 rows x 128 cols, 256 threads, 8x8 register tile each.
__global__ void __launch_bounds__(256) k_gemm1(const float* __restrict__ W1,
                                               const float* __restrict__ b1) {
    __shared__ float sA[DIN * 128];   // [k][row] 32 KB
    __shared__ float sB[DIN * DHID];  // [k][col] 32 KB
    int t = threadIdx.x;
    int row0 = blockIdx.x * 128;

    for (int i = t; i < DIN * DHID; i += 256) sB[i] = W1[i];
    for (int i = t; i < 128 * 16; i += 256) {
        int r = i >> 4, kq = i & 15;
        float4 v = make_float4(0.f, 0.f, 0.f, 0.f);
        if (row0 + r < N_NODES)
            v = reinterpret_cast<const float4*>(g_AX + (size_t)(row0 + r) * DIN)[kq];
        sA[(kq * 4 + 0) * 128 + r] = v.x;
        sA[(kq * 4 + 1) * 128 + r] = v.y;
        sA[(kq * 4 + 2) * 128 + r] = v.z;
        sA[(kq * 4 + 3) * 128 + r] = v.w;
    }
    __syncthreads();

    int tc = t & 15, tr = t >> 4;
    int c0 = tc * 8, r0 = tr * 8;
    float acc[8][8];
    #pragma unroll
    for (int r = 0; r < 8; r++)
        #pragma unroll
        for (int c = 0; c < 8; c++) acc[r][c] = 0.f;

    #pragma unroll 4
    for (int k = 0; k < DIN; k++) {
        float4 a0 = *reinterpret_cast<float4*>(&sA[k * 128 + r0]);
        float4 a1 = *reinterpret_cast<float4*>(&sA[k * 128 + r0 + 4]);
        float4 q0 = *reinterpret_cast<float4*>(&sB[k * DHID + c0]);
        float4 q1 = *reinterpret_cast<float4*>(&sB[k * DHID + c0 + 4]);
        float a[8] = {a0.x, a0.y, a0.z, a0.w, a1.x, a1.y, a1.z, a1.w};
        float b[8] = {q0.x, q0.y, q0.z, q0.w, q1.x, q1.y, q1.z, q1.w};
        #pragma unroll
        for (int r = 0; r < 8; r++)
            #pragma unroll
            for (int c = 0; c < 8; c++) acc[r][c] = fmaf(a[r], b[c], acc[r][c]);
    }

    float bias[8];
    #pragma unroll
    for (int c = 0; c < 8; c++) bias[c] = __ldg(&b1[c0 + c]);

    #pragma unroll
    for (int r = 0; r < 8; r++) {
        int grow = row0 + r0 + r;
        if (grow >= N_NODES) break;
        float4 o0, o1;
        o0.x = fmaxf(acc[r][0] + bias[0], 0.f);
        o0.y = fmaxf(acc[r][1] + bias[1], 0.f);
        o0.z = fmaxf(acc[r][2] + bias[2], 0.f);
        o0.w = fmaxf(acc[r][3] + bias[3], 0.f);
        o1.x = fmaxf(acc[r][4] + bias[4], 0.f);
        o1.y = fmaxf(acc[r][5] + bias[5], 0.f);
        o1.z = fmaxf(acc[r][6] + bias[6], 0.f);
        o1.w = fmaxf(acc[r][7] + bias[7], 0.f);
        float* dstp = g_H + (size_t)grow * DHID + c0;
        reinterpret_cast<float4*>(dstp)[0] = o0;
        reinterpret_cast<float4*>(dstp)[1] = o1;
    }
}

// ---------------------------------------------------------------------------
// GEMM2: G[N,64] = H[N,128] @ W2[128,64]
// Block: 128 rows x 64 cols, 256 threads, 8x4 tile, K in two 64-chunks.
__global__ void __launch_bounds__(256) k_gemm2(const float* __restrict__ W2) {
    __shared__ float sA[64 * 128];    // [k-chunk][row] 32 KB
    __shared__ float sB[DHID * DOUT]; // [k][col] 32 KB
    int t = threadIdx.x;
    int row0 = blockIdx.x * 128;

    for (int i = t; i < DHID * DOUT; i += 256) sB[i] = W2[i];

    int tc = t & 15, tr = t >> 4;
    int c0 = tc * 4, r0 = tr * 8;
    float acc[8][4];
    #pragma unroll
    for (int r = 0; r < 8; r++)
        #pragma unroll
        for (int c = 0; c < 4; c++) acc[r][c] = 0.f;

    #pragma unroll
    for (int ch = 0; ch < 2; ch++) {
        __syncthreads();
        for (int i = t; i < 128 * 16; i += 256) {
            int r = i >> 4, kq = i & 15;
            float4 v = make_float4(0.f, 0.f, 0.f, 0.f);
            if (row0 + r < N_NODES)
                v = reinterpret_cast<const float4*>(g_H + (size_t)(row0 + r) * DHID)
                        [ch * 16 + kq];
            sA[(kq * 4 + 0) * 128 + r] = v.x;
            sA[(kq * 4 + 1) * 128 + r] = v.y;
            sA[(kq * 4 + 2) * 128 + r] = v.z;
            sA[(kq * 4 + 3) * 128 + r] = v.w;
        }
        __syncthreads();

        #pragma unroll 4
        for (int k = 0; k < 64; k++) {
            float4 a0 = *reinterpret_cast<float4*>(&sA[k * 128 + r0]);
            float4 a1 = *reinterpret_cast<float4*>(&sA[k * 128 + r0 + 4]);
            float4 q0 = *reinterpret_cast<float4*>(&sB[(ch * 64 + k) * DOUT + c0]);
            float a[8] = {a0.x, a0.y, a0.z, a0.w, a1.x, a1.y, a1.z, a1.w};
            float b[4] = {q0.x, q0.y, q0.z, q0.w};
            #pragma unroll
            for (int r = 0; r < 8; r++)
                #pragma unroll
                for (int c = 0; c < 4; c++) acc[r][c] = fmaf(a[r], b[c], acc[r][c]);
        }
    }

    #pragma unroll
    for (int r = 0; r < 8; r++) {
        int grow = row0 + r0 + r;
        if (grow >= N_NODES) break;
        float4 gv = make_float4(acc[r][0], acc[r][1], acc[r][2], acc[r][3]);
        reinterpret_cast<float4*>(g_G + (size_t)grow * DOUT + c0)[0] = gv;
    }
}

// ---------------------------------------------------------------------------
extern "C" void kernel_launch(void* const* d_in, const int* in_sizes, int n_in,
                              void* d_out, int out_size) {
    const float* x  = (const float*)d_in[0];
    const int*   ei = (const int*)d_in[1];      // [2, E]
    const float* W1 = (const float*)d_in[2];
    const float* b1 = (const float*)d_in[3];
    const float* W2 = (const float*)d_in[4];
    const float* b2 = (const float*)d_in[5];
    float* out = (float*)d_out;

    const int* src = ei;
    const int* dst = ei + N_EDGES;

    // CSR build (reused by both layers) + dinv
    int* degi_ptr = nullptr;
    cudaGetSymbolAddress((void**)&degi_ptr, g_degi);
    cudaMemsetAsync(degi_ptr, 0, N_NODES * sizeof(int));

    k_count <<<(N_EDGES / 2 + 255) / 256, 256>>>(dst);
    k_scan1 <<<SCAN_NB, SCAN_BS>>>();
    k_scan3 <<<(N_NODES + 255) / 256, 256>>>();
    k_fill  <<<(N_EDGES / 2 + 255) / 256, 256>>>(src, dst);

    // layer 1: pull-aggregate x, then GEMM (+bias+relu fused)
    k_aggX  <<<(N_NODES + 7) / 8, 256>>>(x);
    k_gemm1 <<<(N_NODES + 127) / 128, 256>>>(W1, b1);

    // layer 2: GEMM (128 -> 64), then pull-aggregate into out (+bias fused)
    k_gemm2 <<<(N_NODES + 127) / 128, 256>>>(W2);
    k_agg2  <<<(N_NODES + 7) / 8, 256>>>(b2, out);
}

// round 15
// speedup vs baseline: 1.2432x; 1.0021x over previous
#include <cuda_runtime.h>
#include <cuda_bf16.h>

// ---------------------------------------------------------------------------
// GNN_23630910062676: 2-layer GCN, pull-based aggregation via CSR.
//   degi histogram (with tickets) -> exclusive scan -> atomic-free bucket fill
//   AX[n] = dinv[n]*(dinv[n]*x[n] + sum_s dinv[s]*x[s])
//   H = relu(AX @ W1 + b1) ; G = H @ W2
//   out[n] = b2 + dinv[n]*(dinv[n]*G[n] + sum_s dinv[s]*G[s])
// R15: 4-way ILP batching in count/fill, 8-way unrolled agg gather loops.
// ---------------------------------------------------------------------------

#define N_NODES 50000
#define N_EDGES 800000
#define DIN  64
#define DHID 128
#define DOUT 64
#define EQ   (N_EDGES / 4)     // 200000

#define SCAN_BS 512
#define SCAN_NB ((N_NODES + SCAN_BS - 1) / SCAN_BS)   // 98

__device__ int   g_degi[N_NODES];
__device__ int   g_off [N_NODES + 1];
__device__ int   g_bsum[SCAN_NB];
__device__ int   g_tick[N_EDGES];
__device__ int   g_col [N_EDGES];
__device__ float g_dinv[N_NODES];
__device__ float g_AX  [N_NODES * DIN];
__device__ float g_H   [N_NODES * DHID];
__device__ float g_G   [N_NODES * DOUT];

// ---------------------------------------------------------------------------
// Histogram + tickets, 4 independent edges per thread.
__global__ void k_count(const int* __restrict__ dst) {
    int e = blockIdx.x * blockDim.x + threadIdx.x;
    if (e >= EQ) return;
    int d0 = dst[e], d1 = dst[e + EQ], d2 = dst[e + 2 * EQ], d3 = dst[e + 3 * EQ];
    int t0 = atomicAdd(&g_degi[d0], 1);
    int t1 = atomicAdd(&g_degi[d1], 1);
    int t2 = atomicAdd(&g_degi[d2], 1);
    int t3 = atomicAdd(&g_degi[d3], 1);
    g_tick[e]          = t0;
    g_tick[e + EQ]     = t1;
    g_tick[e + 2 * EQ] = t2;
    g_tick[e + 3 * EQ] = t3;
}

// Per-block inclusive scan, writes block-exclusive offsets + raw block sums
__global__ void k_scan1() {
    __shared__ int sh[SCAN_BS];
    int gid = blockIdx.x * SCAN_BS + threadIdx.x;
    int v = (gid < N_NODES) ? g_degi[gid] : 0;
    sh[threadIdx.x] = v;
    __syncthreads();
    #pragma unroll
    for (int off = 1; off < SCAN_BS; off <<= 1) {
        int t = (threadIdx.x >= off) ? sh[threadIdx.x - off] : 0;
        __syncthreads();
        sh[threadIdx.x] += t;
        __syncthreads();
    }
    if (gid < N_NODES) g_off[gid] = sh[threadIdx.x] - v;   // exclusive within block
    if (threadIdx.x == SCAN_BS - 1) g_bsum[blockIdx.x] = sh[SCAN_BS - 1];
}

// Finalize: each 256-node block reduces its own bsum prefix, then offsets+dinv.
__global__ void k_scan3() {
    __shared__ int sred[256];
    int t = threadIdx.x;
    int need = blockIdx.x >> 1;
    int v = (t < need) ? g_bsum[t] : 0;      // need <= 97 < 256
    sred[t] = v;
    __syncthreads();
    #pragma unroll
    for (int off = 128; off >= 1; off >>= 1) {
        if (t < off) sred[t] += sred[t + off];
        __syncthreads();
    }
    int prefix = sred[0];
    int i = blockIdx.x * 256 + t;
    if (i < N_NODES) {
        g_off[i] = g_off[i] + prefix;
        g_dinv[i] = rsqrtf((float)(g_degi[i] + 1));
    }
    if (i == 0) g_off[N_NODES] = N_EDGES;
}

// Atomic-free fill using tickets, 4 independent edges per thread.
__global__ void k_fill(const int* __restrict__ src, const int* __restrict__ dst) {
    int e = blockIdx.x * blockDim.x + threadIdx.x;
    if (e >= EQ) return;
    int d0 = dst[e], d1 = dst[e + EQ], d2 = dst[e + 2 * EQ], d3 = dst[e + 3 * EQ];
    int t0 = g_tick[e], t1 = g_tick[e + EQ], t2 = g_tick[e + 2 * EQ], t3 = g_tick[e + 3 * EQ];
    int o0 = g_off[d0], o1 = g_off[d1], o2 = g_off[d2], o3 = g_off[d3];
    int s0 = src[e], s1 = src[e + EQ], s2 = src[e + 2 * EQ], s3 = src[e + 3 * EQ];
    g_col[o0 + t0] = s0;
    g_col[o1 + t1] = s1;
    g_col[o2 + t2] = s2;
    g_col[o3 + t3] = s3;
}

// ---------------------------------------------------------------------------
// Pull aggregation over a 64-wide tensor: ONE WARP per node, float2 per lane.
// 8-way + 4-way + scalar unrolled neighbor loop for MLP.
#define AGG_GATHER4(BASE)                                                       \
        int s0 = g_col[BASE], s1 = g_col[BASE + 1],                             \
            s2 = g_col[BASE + 2], s3 = g_col[BASE + 3];                         \
        float d0 = g_dinv[s0], d1 = g_dinv[s1], d2 = g_dinv[s2], d3 = g_dinv[s3]; \
        float2 u0 = SRC2[(size_t)s0 * 32 + l];                                  \
        float2 u1 = SRC2[(size_t)s1 * 32 + l];                                  \
        float2 u2 = SRC2[(size_t)s2 * 32 + l];                                  \
        float2 u3 = SRC2[(size_t)s3 * 32 + l];                                  \
        ax = fmaf(u0.x, d0, ax); ay = fmaf(u0.y, d0, ay);                       \
        ax = fmaf(u1.x, d1, ax); ay = fmaf(u1.y, d1, ay);                       \
        ax = fmaf(u2.x, d2, ax); ay = fmaf(u2.y, d2, ay);                       \
        ax = fmaf(u3.x, d3, ax); ay = fmaf(u3.y, d3, ay);

#define AGG_BODY(SRC2, EPILOGUE)                                                \
    int n = blockIdx.x * 8 + (threadIdx.x >> 5);                                \
    if (n >= N_NODES) return;                                                   \
    int l = threadIdx.x & 31;                                                   \
    float dn = g_dinv[n];                                                       \
    float2 v = SRC2[(size_t)n * 32 + l];                                        \
    float ax = v.x * dn, ay = v.y * dn;                                         \
    int e = g_off[n], end = g_off[n + 1];                                       \
    for (; e + 8 <= end; e += 8) {                                              \
        int p0 = g_col[e],     p1 = g_col[e + 1], p2 = g_col[e + 2], p3 = g_col[e + 3]; \
        int p4 = g_col[e + 4], p5 = g_col[e + 5], p6 = g_col[e + 6], p7 = g_col[e + 7]; \
        float e0 = g_dinv[p0], e1 = g_dinv[p1], e2 = g_dinv[p2], e3 = g_dinv[p3]; \
        float e4 = g_dinv[p4], e5 = g_dinv[p5], e6 = g_dinv[p6], e7 = g_dinv[p7]; \
        float2 w0 = SRC2[(size_t)p0 * 32 + l];                                  \
        float2 w1 = SRC2[(size_t)p1 * 32 + l];                                  \
        float2 w2 = SRC2[(size_t)p2 * 32 + l];                                  \
        float2 w3 = SRC2[(size_t)p3 * 32 + l];                                  \
        float2 w4 = SRC2[(size_t)p4 * 32 + l];                                  \
        float2 w5 = SRC2[(size_t)p5 * 32 + l];                                  \
        float2 w6 = SRC2[(size_t)p6 * 32 + l];                                  \
        float2 w7 = SRC2[(size_t)p7 * 32 + l];                                  \
        ax = fmaf(w0.x, e0, ax); ay = fmaf(w0.y, e0, ay);                       \
        ax = fmaf(w1.x, e1, ax); ay = fmaf(w1.y, e1, ay);                       \
        ax = fmaf(w2.x, e2, ax); ay = fmaf(w2.y, e2, ay);                       \
        ax = fmaf(w3.x, e3, ax); ay = fmaf(w3.y, e3, ay);                       \
        ax = fmaf(w4.x, e4, ax); ay = fmaf(w4.y, e4, ay);                       \
        ax = fmaf(w5.x, e5, ax); ay = fmaf(w5.y, e5, ay);                       \
        ax = fmaf(w6.x, e6, ax); ay = fmaf(w6.y, e6, ay);                       \
        ax = fmaf(w7.x, e7, ax); ay = fmaf(w7.y, e7, ay);                       \
    }                                                                           \
    if (e + 4 <= end) {                                                         \
        AGG_GATHER4(e)                                                          \
        e += 4;                                                                 \
    }                                                                           \
    for (; e < end; e++) {                                                      \
        int s = g_col[e];                                                       \
        float ds = g_dinv[s];                                                   \
        float2 u = SRC2[(size_t)s * 32 + l];                                    \
        ax = fmaf(u.x, ds, ax); ay = fmaf(u.y, ds, ay);                         \
    }                                                                           \
    EPILOGUE

__global__ void __launch_bounds__(256) k_aggX(const float* __restrict__ x) {
    const float2* SRC2 = reinterpret_cast<const float2*>(x);
    AGG_BODY(SRC2,
             {
                 float2 o = make_float2(ax * dn, ay * dn);
                 reinterpret_cast<float2*>(g_AX)[(size_t)n * 32 + l] = o;
             })
}

__global__ void __launch_bounds__(256) k_agg2(const float* __restrict__ b2,
                                              float* __restrict__ out) {
    const float2* SRC2 = reinterpret_cast<const float2*>(g_G);
    AGG_BODY(SRC2,
             {
                 float2 bb = reinterpret_cast<const float2*>(b2)[l];
                 float2 o = make_float2(fmaf(ax, dn, bb.x), fmaf(ay, dn, bb.y));
                 reinterpret_cast<float2*>(out)[(size_t)n * 32 + l] = o;
             })
}

// ---------------------------------------------------------------------------
// GEMM1: H[N,128] = relu(AX[N,64] @ W1[64,128] + b1)
// Block: 128 rows x 128 cols, 256 threads, 8x8 register tile each.
__global__ void __launch_bounds__(256) k_gemm1(const float* __restrict__ W1,
                                               const float* __restrict__ b1) {
    __shared__ float sA[DIN * 128];   // [k][row] 32 KB
    __shared__ float sB[DIN * DHID];  // [k][col] 32 KB
    int t = threadIdx.x;
    int row0 = blockIdx.x * 128;

    for (int i = t; i < DIN * DHID; i += 256) sB[i] = W1[i];
    for (int i = t; i < 128 * 16; i += 256) {
        int r = i >> 4, kq = i & 15;
        float4 v = make_float4(0.f, 0.f, 0.f, 0.f);
        if (row0 + r < N_NODES)
            v = reinterpret_cast<const float4*>(g_AX + (size_t)(row0 + r) * DIN)[kq];
        sA[(kq * 4 + 0) * 128 + r] = v.x;
        sA[(kq * 4 + 1) * 128 + r] = v.y;
        sA[(kq * 4 + 2) * 128 + r] = v.z;
        sA[(kq * 4 + 3) * 128 + r] = v.w;
    }
    __syncthreads();

    int tc = t & 15, tr = t >> 4;
    int c0 = tc * 8, r0 = tr * 8;
    float acc[8][8];
    #pragma unroll
    for (int r = 0; r < 8; r++)
        #pragma unroll
        for (int c = 0; c < 8; c++) acc[r][c] = 0.f;

    #pragma unroll 4
    for (int k = 0; k < DIN; k++) {
        float4 a0 = *reinterpret_cast<float4*>(&sA[k * 128 + r0]);
        float4 a1 = *reinterpret_cast<float4*>(&sA[k * 128 + r0 + 4]);
        float4 q0 = *reinterpret_cast<float4*>(&sB[k * DHID + c0]);
        float4 q1 = *reinterpret_cast<float4*>(&sB[k * DHID + c0 + 4]);
        float a[8] = {a0.x, a0.y, a0.z, a0.w, a1.x, a1.y, a1.z, a1.w};
        float b[8] = {q0.x, q0.y, q0.z, q0.w, q1.x, q1.y, q1.z, q1.w};
        #pragma unroll
        for (int r = 0; r < 8; r++)
            #pragma unroll
            for (int c = 0; c < 8; c++) acc[r][c] = fmaf(a[r], b[c], acc[r][c]);
    }

    float bias[8];
    #pragma unroll
    for (int c = 0; c < 8; c++) bias[c] = __ldg(&b1[c0 + c]);

    #pragma unroll
    for (int r = 0; r < 8; r++) {
        int grow = row0 + r0 + r;
        if (grow >= N_NODES) break;
        float4 o0, o1;
        o0.x = fmaxf(acc[r][0] + bias[0], 0.f);
        o0.y = fmaxf(acc[r][1] + bias[1], 0.f);
        o0.z = fmaxf(acc[r][2] + bias[2], 0.f);
        o0.w = fmaxf(acc[r][3] + bias[3], 0.f);
        o1.x = fmaxf(acc[r][4] + bias[4], 0.f);
        o1.y = fmaxf(acc[r][5] + bias[5], 0.f);
        o1.z = fmaxf(acc[r][6] + bias[6], 0.f);
        o1.w = fmaxf(acc[r][7] + bias[7], 0.f);
        float* dstp = g_H + (size_t)grow * DHID + c0;
        reinterpret_cast<float4*>(dstp)[0] = o0;
        reinterpret_cast<float4*>(dstp)[1] = o1;
    }
}

// ---------------------------------------------------------------------------
// GEMM2: G[N,64] = H[N,128] @ W2[128,64]
// Block: 128 rows x 64 cols, 256 threads, 8x4 tile, K in two 64-chunks.
__global__ void __launch_bounds__(256) k_gemm2(const float* __restrict__ W2) {
    __shared__ float sA[64 * 128];    // [k-chunk][row] 32 KB
    __shared__ float sB[DHID * DOUT]; // [k][col] 32 KB
    int t = threadIdx.x;
    int row0 = blockIdx.x * 128;

    for (int i = t; i < DHID * DOUT; i += 256) sB[i] = W2[i];

    int tc = t & 15, tr = t >> 4;
    int c0 = tc * 4, r0 = tr * 8;
    float acc[8][4];
    #pragma unroll
    for (int r = 0; r < 8; r++)
        #pragma unroll
        for (int c = 0; c < 4; c++) acc[r][c] = 0.f;

    #pragma unroll
    for (int ch = 0; ch < 2; ch++) {
        __syncthreads();
        for (int i = t; i < 128 * 16; i += 256) {
            int r = i >> 4, kq = i & 15;
            float4 v = make_float4(0.f, 0.f, 0.f, 0.f);
            if (row0 + r < N_NODES)
                v = reinterpret_cast<const float4*>(g_H + (size_t)(row0 + r) * DHID)
                        [ch * 16 + kq];
            sA[(kq * 4 + 0) * 128 + r] = v.x;
            sA[(kq * 4 + 1) * 128 + r] = v.y;
            sA[(kq * 4 + 2) * 128 + r] = v.z;
            sA[(kq * 4 + 3) * 128 + r] = v.w;
        }
        __syncthreads();

        #pragma unroll 4
        for (int k = 0; k < 64; k++) {
            float4 a0 = *reinterpret_cast<float4*>(&sA[k * 128 + r0]);
            float4 a1 = *reinterpret_cast<float4*>(&sA[k * 128 + r0 + 4]);
            float4 q0 = *reinterpret_cast<float4*>(&sB[(ch * 64 + k) * DOUT + c0]);
            float a[8] = {a0.x, a0.y, a0.z, a0.w, a1.x, a1.y, a1.z, a1.w};
            float b[4] = {q0.x, q0.y, q0.z, q0.w};
            #pragma unroll
            for (int r = 0; r < 8; r++)
                #pragma unroll
                for (int c = 0; c < 4; c++) acc[r][c] = fmaf(a[r], b[c], acc[r][c]);
        }
    }

    #pragma unroll
    for (int r = 0; r < 8; r++) {
        int grow = row0 + r0 + r;
        if (grow >= N_NODES) break;
        float4 gv = make_float4(acc[r][0], acc[r][1], acc[r][2], acc[r][3]);
        reinterpret_cast<float4*>(g_G + (size_t)grow * DOUT + c0)[0] = gv;
    }
}

// ---------------------------------------------------------------------------
extern "C" void kernel_launch(void* const* d_in, const int* in_sizes, int n_in,
                              void* d_out, int out_size) {
    const float* x  = (const float*)d_in[0];
    const int*   ei = (const int*)d_in[1];      // [2, E]
    const float* W1 = (const float*)d_in[2];
    const float* b1 = (const float*)d_in[3];
    const float* W2 = (const float*)d_in[4];
    const float* b2 = (const float*)d_in[5];
    float* out = (float*)d_out;

    const int* src = ei;
    const int* dst = ei + N_EDGES;

    // CSR build (reused by both layers) + dinv
    int* degi_ptr = nullptr;
    cudaGetSymbolAddress((void**)&degi_ptr, g_degi);
    cudaMemsetAsync(degi_ptr, 0, N_NODES * sizeof(int));

    k_count <<<(EQ + 255) / 256, 256>>>(dst);
    k_scan1 <<<SCAN_NB, SCAN_BS>>>();
    k_scan3 <<<(N_NODES + 255) / 256, 256>>>();
    k_fill  <<<(EQ + 255) / 256, 256>>>(src, dst);

    // layer 1: pull-aggregate x, then GEMM (+bias+relu fused)
    k_aggX  <<<(N_NODES + 7) / 8, 256>>>(x);
    k_gemm1 <<<(N_NODES + 127) / 128, 256>>>(W1, b1);

    // layer 2: GEMM (128 -> 64), then pull-aggregate into out (+bias fused)
    k_gemm2 <<<(N_NODES + 127) / 128, 256>>>(W2);
    k_agg2  <<<(N_NODES + 7) / 8, 256>>>(b2, out);
}